// round 9
// baseline (speedup 1.0000x reference)
#include <cuda_runtime.h>
#include <cuda_bf16.h>
#include <math.h>
#include <stdint.h>

// ---------------- problem constants ----------------
constexpr int N_   = 20000;   // nodes
constexpr int E_   = 100000;  // edges
constexpr int D_   = 248;     // Lie algebra dim
constexpr int HID_ = 256;     // MLP hidden
constexpr int IN_  = 128;     // input feature dim
constexpr int OUT_ = 16;      // output dim
constexpr int NL_  = 4;       // layers
constexpr int NNZ_ = 512;     // structure constant nnz
constexpr int NB_  = 1024;    // killing form nnz
constexpr int NG_  = 128;     // graphs
constexpr int D2_  = 2 * D_;  // 496
constexpr int DP1_ = D_ + 1;  // 249

// ---------------- scratch (device globals; allocation is forbidden) ----------------
__device__ float g_t1[(size_t)N_ * HID_];    // node hidden
__device__ float g_h[(size_t)N_ * D_];       // node features h
__device__ float g_br[(size_t)E_ * D_];      // per-edge Lie bracket
__device__ float g_eH[(size_t)E_ * HID_];    // edge hidden
__device__ float g_agg[(size_t)N_ * D_];     // aggregated messages
__device__ float g_pooled[NG_ * DP1_];
__device__ float g_cnt[NG_];

// pre-packed weights: B-operand layout [N][Kp] bf16, hi/lo split
constexpr size_t OFF_WI1 = 0;                        // N=256, Kp=128
constexpr size_t OFF_WI2 = OFF_WI1 + 256 * 128;      // N=248, Kp=256
constexpr size_t OFF_L0  = OFF_WI2 + 248 * 256;
constexpr size_t LSTRIDE = 256 * 512 + 248 * 256 + 256 * 512 + 248 * 256;
constexpr size_t WP_TOTAL = OFF_L0 + 4 * LSTRIDE;
__device__ __nv_bfloat16 g_wpHi[WP_TOTAL];
__device__ __nv_bfloat16 g_wpLo[WP_TOTAL];

__device__ __forceinline__ float silu_f(float v) {
    return v / (1.0f + expf(-v));
}
__device__ __forceinline__ uint32_t pack_bf16(float a, float b) {
    __nv_bfloat162 t = __floats2bfloat162_rn(a, b);   // a -> low, b -> high
    return *(uint32_t*)&t;
}
__device__ __forceinline__ float bf16_round(float x) {
    return __bfloat162float(__float2bfloat16(x));
}
__device__ __forceinline__ uint32_t smem_to_u32(const void* p) {
    uint32_t a;
    asm("{ .reg .u64 t; cvta.to.shared.u64 t, %1; cvt.u32.u64 %0, t; }"
        : "=r"(a) : "l"(p));
    return a;
}
#define LDSM_X4(r, a)                                                          \
    asm volatile("ldmatrix.sync.aligned.m8n8.x4.shared.b16 {%0,%1,%2,%3}, [%4];" \
                 : "=r"((r)[0]), "=r"((r)[1]), "=r"((r)[2]), "=r"((r)[3])      \
                 : "r"(a))

// ---------------- weight prepack: W[K][N] fp32 -> P[N][Kp] bf16 hi/lo ----------------
__global__ void prepack_kernel(const float* __restrict__ W,
                               __nv_bfloat16* __restrict__ hi,
                               __nv_bfloat16* __restrict__ lo,
                               int K, int N, int Kp)
{
    int idx = blockIdx.x * 256 + threadIdx.x;
    if (idx >= N * Kp) return;
    int n = idx / Kp, k = idx - n * Kp;
    float v = (k < K) ? __ldg(&W[(size_t)k * N + n]) : 0.0f;
    __nv_bfloat16 h = __float2bfloat16(v);
    hi[idx] = h;
    lo[idx] = __float2bfloat16(v - __bfloat162float(h));
}

// ---------------- 3xBF16 mma.sync GEMM with ldmatrix frags + prepacked weights -----
// C = act(A @ W + bias) (+ res)   OR  (scatter mode, dstIdx != null):
//     atomicAdd(C[dstIdx[m] * N + n], (A@W + bias)[m,n])
// A cols [0,K1) from A1 (row gathered via gidx if non-null), [K1,K) from A2.
// B prepacked [N][Kp] bf16 hi/lo, Kp padded to mult of 16, zero-filled beyond K.
// Requires K % 8 == 0, K1 % 8 == 0.
constexpr int BM = 128, BN = 128, BK = 16;
// smem: 4 regions (AH, AL, BH, BL), each 2 buffers of 128 rows x 48B (16 bf16 + pad)
constexpr uint32_t ROWB   = 48;
constexpr uint32_t BUFSZ  = 128 * ROWB;            // 6144
constexpr uint32_t OFF_AH = 0;
constexpr uint32_t OFF_AL = 2 * BUFSZ;
constexpr uint32_t OFF_BH = 4 * BUFSZ;
constexpr uint32_t OFF_BL = 6 * BUFSZ;
constexpr uint32_t SMEM_DYN = 8 * BUFSZ;           // 49152

__global__ __launch_bounds__(256, 2) void gemm_3xbf16(
    const float* __restrict__ A1, const int* __restrict__ gidx,
    const float* __restrict__ A2, int K1,
    const __nv_bfloat16* __restrict__ Bhi, const __nv_bfloat16* __restrict__ Blo, int Kp,
    const float* __restrict__ bias, const float* __restrict__ res,
    const int* __restrict__ dstIdx, float* __restrict__ C,
    int M, int N, int K, int act)
{
    extern __shared__ uint8_t smem[];
    const uint32_t s0 = smem_to_u32(smem);

    const int tid  = threadIdx.x;
    const int lane = tid & 31;
    const int wid  = tid >> 5;
    const int row0 = blockIdx.y * BM;
    const int col0 = blockIdx.x * BN;

    // ---- staging mappings ----
    const int r  = tid >> 1;     // 0..127 (A row / B n-row)
    const int hh = tid & 1;      // A: k-half (0/1); B: hi(0)/lo(1) select

    const int gmA = row0 + r;
    const bool av = gmA < M;
    size_t a1off = 0, a2off = 0;
    if (av) {
        int rr = gidx ? __ldg(&gidx[gmA]) : gmA;
        a1off = (size_t)rr * K1;
        a2off = (size_t)gmA * (K - K1);
    }
    const int gnB = col0 + r;
    const bool bv = gnB < N;
    const size_t boff = (size_t)gnB * Kp;
    const __nv_bfloat16* Bsel = hh ? Blo : Bhi;

    // warp tile: 32 (m) x 64 (n); warps 4x2
    const int wm = (wid & 3) * 32;
    const int wn = (wid >> 2) * 64;
    const int grp = lane >> 3;     // ldmatrix matrix index 0..3
    const int lr  = lane & 7;      // row within matrix
    const int g4  = lane >> 2;     // mma row group 0..7
    const int qid = lane & 3;

    // ldmatrix source addresses (buffer 0; add buf*BUFSZ at use)
    // A matrices per mt: 0:(m,k0) 1:(m+8,k0) 2:(m,k8) 3:(m+8,k8)
    uint32_t aAH[2], aAL[2];
    #pragma unroll
    for (int mt = 0; mt < 2; mt++) {
        const uint32_t arow = wm + 16 * mt + (grp & 1) * 8 + lr;
        const uint32_t akb  = (grp >> 1) * 16;
        aAH[mt] = s0 + OFF_AH + arow * ROWB + akb;
        aAL[mt] = s0 + OFF_AL + arow * ROWB + akb;
    }
    // B matrices per n-pair np: 0:(n0-7,k0) 1:(n0-7,k8) 2:(n8-15,k0) 3:(n8-15,k8)
    const uint32_t brow0 = wn + (grp >> 1) * 8 + lr;
    const uint32_t bkb   = (grp & 1) * 16;
    const uint32_t bBH0  = s0 + OFF_BH + brow0 * ROWB + bkb;
    const uint32_t bBL0  = s0 + OFF_BL + brow0 * ROWB + bkb;

    float acc[2][8][4];
    #pragma unroll
    for (int mt = 0; mt < 2; mt++)
        #pragma unroll
        for (int nt = 0; nt < 8; nt++)
            #pragma unroll
            for (int c = 0; c < 4; c++) acc[mt][nt][c] = 0.0f;

    float4 aV0, aV1;
    uint4 bU0, bU1;
    auto prefetch = [&](int k0) {
        const int kg = k0 + hh * 8;
        if (av && kg < K) {
            const float* p = (kg < K1) ? &A1[a1off + kg] : &A2[a2off + (kg - K1)];
            aV0 = *(const float4*)p;
            aV1 = *(const float4*)(p + 4);
        } else {
            aV0 = make_float4(0.f, 0.f, 0.f, 0.f);
            aV1 = make_float4(0.f, 0.f, 0.f, 0.f);
        }
        if (bv) {
            bU0 = *(const uint4*)&Bsel[boff + k0];
            bU1 = *(const uint4*)&Bsel[boff + k0 + 8];
        } else {
            bU0 = make_uint4(0, 0, 0, 0);
            bU1 = make_uint4(0, 0, 0, 0);
        }
    };
    auto stage = [&](int buf) {
        // A: bf16 hi/lo split, row-major [row][k], 16B per k-half
        float f[8] = {aV0.x, aV0.y, aV0.z, aV0.w, aV1.x, aV1.y, aV1.z, aV1.w};
        uint32_t hw[4], lw[4];
        #pragma unroll
        for (int q = 0; q < 4; q++) {
            float h0 = bf16_round(f[2 * q]), h1 = bf16_round(f[2 * q + 1]);
            hw[q] = pack_bf16(h0, h1);
            lw[q] = pack_bf16(f[2 * q] - h0, f[2 * q + 1] - h1);
        }
        const uint32_t ao = buf * BUFSZ + r * ROWB + hh * 16;
        *(uint4*)(smem + OFF_AH + ao) = make_uint4(hw[0], hw[1], hw[2], hw[3]);
        *(uint4*)(smem + OFF_AL + ao) = make_uint4(lw[0], lw[1], lw[2], lw[3]);
        // B: straight copy of a 32B prepacked row (hi via hh=0 threads, lo via hh=1)
        const uint32_t bo = (hh ? OFF_BL : OFF_BH) + buf * BUFSZ + r * ROWB;
        *(uint4*)(smem + bo)      = bU0;
        *(uint4*)(smem + bo + 16) = bU1;
    };

    // prologue: stage tile 0, prefetch tile 1
    prefetch(0);
    stage(0);
    if (BK < Kp) prefetch(BK);
    __syncthreads();

    const int nTiles = Kp / BK;
    for (int t = 0; t < nTiles; t++) {
        const int buf = t & 1;
        if (t + 1 < nTiles) stage(buf ^ 1);
        if (t + 2 < nTiles) prefetch((t + 2) * BK);

        const uint32_t bufo = buf * BUFSZ;
        uint32_t ah[2][4], al[2][4];
        #pragma unroll
        for (int mt = 0; mt < 2; mt++) {
            LDSM_X4(ah[mt], aAH[mt] + bufo);
            LDSM_X4(al[mt], aAL[mt] + bufo);
        }
        #pragma unroll
        for (int np = 0; np < 4; np++) {
            uint32_t bh[4], bl[4];
            LDSM_X4(bh, bBH0 + bufo + np * 16 * ROWB);
            LDSM_X4(bl, bBL0 + bufo + np * 16 * ROWB);
            #pragma unroll
            for (int sub = 0; sub < 2; sub++) {
                const int nt = np * 2 + sub;
                const uint32_t bh0 = bh[sub * 2], bh1 = bh[sub * 2 + 1];
                const uint32_t bl0 = bl[sub * 2], bl1 = bl[sub * 2 + 1];
                #pragma unroll
                for (int mt = 0; mt < 2; mt++) {
                    #define MMA_BF16(Afr, B0, B1)                                      \
                        asm volatile(                                                  \
                            "mma.sync.aligned.m16n8k16.row.col.f32.bf16.bf16.f32 "     \
                            "{%0,%1,%2,%3}, {%4,%5,%6,%7}, {%8,%9}, {%0,%1,%2,%3};"    \
                            : "+f"(acc[mt][nt][0]), "+f"(acc[mt][nt][1]),              \
                              "+f"(acc[mt][nt][2]), "+f"(acc[mt][nt][3])               \
                            : "r"(Afr[mt][0]), "r"(Afr[mt][1]),                        \
                              "r"(Afr[mt][2]), "r"(Afr[mt][3]),                        \
                              "r"(B0), "r"(B1))
                    MMA_BF16(ah, bh0, bh1);   // hi * hi
                    MMA_BF16(al, bh0, bh1);   // lo * hi
                    MMA_BF16(ah, bl0, bl1);   // hi * lo
                    #undef MMA_BF16
                }
            }
        }
        __syncthreads();
    }

    // ---- epilogue ----
    #pragma unroll
    for (int mt = 0; mt < 2; mt++) {
        #pragma unroll
        for (int rr = 0; rr < 2; rr++) {
            const int gm = row0 + wm + 16 * mt + g4 + rr * 8;
            if (gm >= M) continue;
            int drow = 0;
            if (dstIdx) drow = __ldg(&dstIdx[gm]);
            #pragma unroll
            for (int nt = 0; nt < 8; nt++) {
                const int gn = col0 + wn + 8 * nt + qid * 2;
                if (gn >= N) continue;   // N even, pair aligned
                float2 bb = __ldg((const float2*)&bias[gn]);
                float v0 = acc[mt][nt][rr * 2 + 0] + bb.x;
                float v1 = acc[mt][nt][rr * 2 + 1] + bb.y;
                if (act) { v0 = silu_f(v0); v1 = silu_f(v1); }
                if (dstIdx) {
                    atomicAdd(&C[(size_t)drow * N + gn],     v0);
                    atomicAdd(&C[(size_t)drow * N + gn + 1], v1);
                } else {
                    if (res) {
                        float2 rv = *(const float2*)&res[(size_t)gm * N + gn];
                        v0 += rv.x; v1 += rv.y;
                    }
                    *(float2*)&C[(size_t)gm * N + gn] = make_float2(v0, v1);
                }
            }
        }
    }
}

// ---------------- edge gather + Lie bracket -> br (8 edges/block, warp/edge) ----
constexpr int EPB = 8;
__global__ __launch_bounds__(256) void edge_bracket_kernel(
    const float* __restrict__ h, const int* __restrict__ ei,
    const int* __restrict__ sci, const int* __restrict__ scj,
    const int* __restrict__ sck, const float* __restrict__ scc,
    float* __restrict__ br)
{
    __shared__ int   s_i[NNZ_], s_j[NNZ_], s_k[NNZ_];
    __shared__ float s_c[NNZ_];
    __shared__ float hs[EPB][D_], hd[EPB][D_], brs[EPB][D_];

    const int tid = threadIdx.x;
    for (int t = tid; t < NNZ_; t += 256) {
        s_i[t] = __ldg(&sci[t]);
        s_j[t] = __ldg(&scj[t]);
        s_k[t] = __ldg(&sck[t]);
        s_c[t] = __ldg(&scc[t]);
    }
    __syncthreads();

    const int w = tid >> 5, lane = tid & 31;
    const int e = blockIdx.x * EPB + w;
    if (e >= E_) return;
    const int s = __ldg(&ei[e]);
    const int d = __ldg(&ei[E_ + e]);

    const float4* hsrc = (const float4*)(h + (size_t)s * D_);
    const float4* hdst = (const float4*)(h + (size_t)d * D_);
    #pragma unroll
    for (int q = lane; q < D_ / 4; q += 32) {
        ((float4*)hs[w])[q] = hsrc[q];
        ((float4*)hd[w])[q] = hdst[q];
    }
    for (int k = lane; k < D_; k += 32) brs[w][k] = 0.0f;
    __syncwarp();

    #pragma unroll
    for (int t = lane; t < NNZ_; t += 32) {
        float v = s_c[t] * hs[w][s_i[t]] * hd[w][s_j[t]];
        atomicAdd(&brs[w][s_k[t]], v);
    }
    __syncwarp();

    float4* row = (float4*)(br + (size_t)e * D_);
    #pragma unroll
    for (int q = lane; q < D_ / 4; q += 32)
        row[q] = ((const float4*)brs[w])[q];
}

__global__ void zero_kernel(float* __restrict__ p, size_t n) {
    size_t idx = (size_t)blockIdx.x * blockDim.x + threadIdx.x;
    if (idx < n) p[idx] = 0.0f;
}

// ---------------- killing form + pooling (scatter to graphs) ----------------
__global__ __launch_bounds__(128) void killing_pool_kernel(
    const float* __restrict__ h, const int* __restrict__ batch,
    const int* __restrict__ kbr, const int* __restrict__ kbc,
    const float* __restrict__ kbv,
    float* __restrict__ pooled, float* __restrict__ cnt)
{
    const int n = blockIdx.x;
    __shared__ float hrow[D_];
    __shared__ float wsum[4];
    for (int k = threadIdx.x; k < D_; k += 128)
        hrow[k] = h[(size_t)n * D_ + k];
    __syncthreads();

    float s = 0.0f;
    for (int t = threadIdx.x; t < NB_; t += 128)
        s += __ldg(&kbv[t]) * hrow[__ldg(&kbr[t])] * hrow[__ldg(&kbc[t])];
    #pragma unroll
    for (int off = 16; off > 0; off >>= 1)
        s += __shfl_down_sync(0xffffffffu, s, off);
    if ((threadIdx.x & 31) == 0) wsum[threadIdx.x >> 5] = s;
    __syncthreads();

    const int b = __ldg(&batch[n]);
    for (int k = threadIdx.x; k < D_; k += 128)
        atomicAdd(&pooled[b * DP1_ + k], hrow[k]);
    if (threadIdx.x == 0) {
        float ks = wsum[0] + wsum[1] + wsum[2] + wsum[3];
        atomicAdd(&pooled[b * DP1_ + D_], ks);
        atomicAdd(&cnt[b], 1.0f);
    }
}

// ---------------- final MLP per graph ----------------
__global__ __launch_bounds__(256) void final_mlp_kernel(
    const float* __restrict__ pooled, const float* __restrict__ cnt,
    const float* __restrict__ Wo1, const float* __restrict__ bo1,
    const float* __restrict__ Wo2, const float* __restrict__ bo2,
    float* __restrict__ out)
{
    const int g = blockIdx.x;
    __shared__ float p[DP1_];
    __shared__ float hid[HID_];
    const float c = fmaxf(cnt[g], 1.0f);
    for (int k = threadIdx.x; k < DP1_; k += 256)
        p[k] = pooled[g * DP1_ + k] / c;
    __syncthreads();

    const int j = threadIdx.x;
    float s = __ldg(&bo1[j]);
    for (int k = 0; k < DP1_; k++)
        s = fmaf(p[k], __ldg(&Wo1[k * HID_ + j]), s);
    hid[j] = silu_f(s);
    __syncthreads();

    if (j < OUT_) {
        float o = __ldg(&bo2[j]);
        for (int k = 0; k < HID_; k++)
            o = fmaf(hid[k], __ldg(&Wo2[k * OUT_ + j]), o);
        out[g * OUT_ + j] = o;
    }
}

// ---------------- host driver ----------------
static inline dim3 gemm_grid(int M, int N) {
    return dim3((N + BN - 1) / BN, (M + BM - 1) / BM);
}

extern "C" void kernel_launch(void* const* d_in, const int* in_sizes, int n_in,
                              void* d_out, int out_size)
{
    const float* x     = (const float*)d_in[0];
    const int*   ei    = (const int*)  d_in[1];
    const int*   batch = (const int*)  d_in[2];
    const int*   sci   = (const int*)  d_in[3];
    const int*   scj   = (const int*)  d_in[4];
    const int*   sck   = (const int*)  d_in[5];
    const float* scc   = (const float*)d_in[6];
    const int*   kbr   = (const int*)  d_in[7];
    const int*   kbc   = (const int*)  d_in[8];
    const float* kbv   = (const float*)d_in[9];
    const float* Wi1   = (const float*)d_in[10];
    const float* bi1   = (const float*)d_in[11];
    const float* Wi2   = (const float*)d_in[12];
    const float* bi2   = (const float*)d_in[13];
    const float* msgW1 = (const float*)d_in[14];
    const float* msgb1 = (const float*)d_in[15];
    const float* msgW2 = (const float*)d_in[16];
    const float* msgb2 = (const float*)d_in[17];
    const float* updW1 = (const float*)d_in[18];
    const float* updb1 = (const float*)d_in[19];
    const float* updW2 = (const float*)d_in[20];
    const float* updb2 = (const float*)d_in[21];
    const float* Wo1   = (const float*)d_in[22];
    const float* bo1   = (const float*)d_in[23];
    const float* Wo2   = (const float*)d_in[24];
    const float* bo2   = (const float*)d_in[25];

    float *t1, *h, *br, *eH, *agg, *pooled, *cnt;
    __nv_bfloat16 *wpHi, *wpLo;
    cudaGetSymbolAddress((void**)&t1,     g_t1);
    cudaGetSymbolAddress((void**)&h,      g_h);
    cudaGetSymbolAddress((void**)&br,     g_br);
    cudaGetSymbolAddress((void**)&eH,     g_eH);
    cudaGetSymbolAddress((void**)&agg,    g_agg);
    cudaGetSymbolAddress((void**)&pooled, g_pooled);
    cudaGetSymbolAddress((void**)&cnt,    g_cnt);
    cudaGetSymbolAddress((void**)&wpHi,   g_wpHi);
    cudaGetSymbolAddress((void**)&wpLo,   g_wpLo);

    cudaFuncSetAttribute(gemm_3xbf16, cudaFuncAttributeMaxDynamicSharedMemorySize, (int)SMEM_DYN);

    const int* src = ei;
    const int* dst = ei + E_;

    // ---- prepack all weights into bf16 hi/lo B-operand layout ----
    auto pp = [&](const float* W, int K, int N, int Kp, size_t off) {
        int n = N * Kp;
        prepack_kernel<<<(n + 255) / 256, 256>>>(W, wpHi + off, wpLo + off, K, N, Kp);
    };
    pp(Wi1, IN_,  HID_, 128, OFF_WI1);
    pp(Wi2, HID_, D_,   256, OFF_WI2);
    size_t offs[NL_][4];
    for (int l = 0; l < NL_; l++) {
        size_t b = OFF_L0 + (size_t)l * LSTRIDE;
        offs[l][0] = b;                                      // mW1: N=256, Kp=512
        offs[l][1] = b + 256 * 512;                          // mW2: N=248, Kp=256
        offs[l][2] = b + 256 * 512 + 248 * 256;              // uW1: N=256, Kp=512
        offs[l][3] = b + 256 * 512 + 248 * 256 + 256 * 512;  // uW2: N=248, Kp=256
        pp(msgW1 + (size_t)l * D2_ * HID_, D2_,  HID_, 512, offs[l][0]);
        pp(msgW2 + (size_t)l * HID_ * D_,  HID_, D_,   256, offs[l][1]);
        pp(updW1 + (size_t)l * D2_ * HID_, D2_,  HID_, 512, offs[l][2]);
        pp(updW2 + (size_t)l * HID_ * D_,  HID_, D_,   256, offs[l][3]);
    }

    // ---- input MLP ----
    gemm_3xbf16<<<gemm_grid(N_, HID_), 256, SMEM_DYN>>>(
        x,  nullptr, x,  IN_,  wpHi + OFF_WI1, wpLo + OFF_WI1, 128,
        bi1, nullptr, nullptr, t1, N_, HID_, IN_,  1);
    gemm_3xbf16<<<gemm_grid(N_, D_),   256, SMEM_DYN>>>(
        t1, nullptr, t1, HID_, wpHi + OFF_WI2, wpLo + OFF_WI2, 256,
        bi2, nullptr, nullptr, h,  N_, D_,   HID_, 0);

    // ---- message passing layers ----
    for (int l = 0; l < NL_; l++) {
        const float* mb1 = msgb1 + (size_t)l * HID_;
        const float* mb2 = msgb2 + (size_t)l * D_;
        const float* ub1 = updb1 + (size_t)l * HID_;
        const float* ub2 = updb2 + (size_t)l * D_;

        edge_bracket_kernel<<<(E_ + EPB - 1) / EPB, 256>>>(h, ei, sci, scj, sck, scc, br);

        // message MLP layer 1: A = [h[src] | br]
        gemm_3xbf16<<<gemm_grid(E_, HID_), 256, SMEM_DYN>>>(
            h, src, br, D_, wpHi + offs[l][0], wpLo + offs[l][0], 512,
            mb1, nullptr, nullptr, eH, E_, HID_, D2_, 1);

        // zero agg, then message MLP layer 2 with fused scatter-add into agg
        {
            size_t n = (size_t)N_ * D_;
            zero_kernel<<<(unsigned)((n + 255) / 256), 256>>>(agg, n);
        }
        gemm_3xbf16<<<gemm_grid(E_, D_), 256, SMEM_DYN>>>(
            eH, nullptr, eH, HID_, wpHi + offs[l][1], wpLo + offs[l][1], 256,
            mb2, nullptr, dst, agg, E_, D_, HID_, 0);

        // update MLP: A = [h | agg]
        gemm_3xbf16<<<gemm_grid(N_, HID_), 256, SMEM_DYN>>>(
            h, nullptr, agg, D_, wpHi + offs[l][2], wpLo + offs[l][2], 512,
            ub1, nullptr, nullptr, t1, N_, HID_, D2_, 1);
        gemm_3xbf16<<<gemm_grid(N_, D_), 256, SMEM_DYN>>>(
            t1, nullptr, t1, HID_, wpHi + offs[l][3], wpLo + offs[l][3], 256,
            ub2, h, nullptr, h, N_, D_, HID_, 0);
    }

    // ---- killing form + pooling ----
    {
        size_t n = NG_ * DP1_;
        zero_kernel<<<(unsigned)((n + 255) / 256), 256>>>(pooled, n);
        zero_kernel<<<1, NG_>>>(cnt, NG_);
    }
    killing_pool_kernel<<<N_, 128>>>(h, batch, kbr, kbc, kbv, pooled, cnt);

    // ---- final MLP ----
    final_mlp_kernel<<<NG_, 256>>>(pooled, cnt, Wo1, bo1, Wo2, bo2, (float*)d_out);
}

// round 10
// speedup vs baseline: 1.1785x; 1.1785x over previous
#include <cuda_runtime.h>
#include <cuda_bf16.h>
#include <math.h>
#include <stdint.h>

// ---------------- problem constants ----------------
constexpr int N_   = 20000;   // nodes
constexpr int E_   = 100000;  // edges
constexpr int D_   = 248;     // Lie algebra dim
constexpr int HID_ = 256;     // MLP hidden
constexpr int IN_  = 128;     // input feature dim
constexpr int OUT_ = 16;      // output dim
constexpr int NL_  = 4;       // layers
constexpr int NNZ_ = 512;     // structure constant nnz
constexpr int NB_  = 1024;    // killing form nnz
constexpr int NG_  = 128;     // graphs
constexpr int D2_  = 2 * D_;  // 496
constexpr int DP1_ = D_ + 1;  // 249

// ---------------- scratch (device globals; allocation is forbidden) ----------------
__device__ float g_t1[(size_t)N_ * HID_];    // node hidden / hw staging
__device__ float g_h[(size_t)N_ * D_];       // node features h
__device__ float g_br[(size_t)E_ * D_];      // per-edge Lie bracket
__device__ float g_eH[(size_t)E_ * HID_];    // edge hidden
__device__ float g_agg[(size_t)N_ * D_];     // aggregated messages
__device__ float g_pooled[NG_ * DP1_];
__device__ float g_cnt[NG_];
__device__ float g_zbias[HID_];              // zero bias for split GEMM

__device__ __forceinline__ float silu_f(float v) {
    return v / (1.0f + expf(-v));
}

__device__ __forceinline__ uint32_t pack_bf16(float a, float b) {
    __nv_bfloat162 t = __floats2bfloat162_rn(a, b);   // a -> low, b -> high
    return *(uint32_t*)&t;
}
__device__ __forceinline__ float bf16_round(float x) {
    return __bfloat162float(__float2bfloat16(x));
}

// ---------------- 3xBF16 tensor-core GEMM, double-buffered, split-K A ----------------
// C = act(A @ W + bias + res) (+)   OR  (scatter mode, dstIdx != null):
//     atomicAdd(C[dstIdx[m] * N + n], (A@W + bias)[m,n])
// Residual is added BEFORE activation; its row is resIdx[m] if resIdx != null, else m.
// A operand columns [0, K1)  from A1 (row gathered via gidx if non-null, stride K1)
// A operand columns [K1, K)  from A2 (direct row, stride K-K1)
// W: K x N row-major. Requires K % 8 == 0, K1 % 8 == 0, N % 4 == 0.
constexpr int BM = 128, BN = 128, BK = 16;
constexpr int PA = 12;   // uint32 words per A smem row (8 pairs + pad, 48B: 16B-aligned)
constexpr int PW = 136;  // uint32 words per W smem p-row (544B: 16B-aligned)

__global__ __launch_bounds__(256, 2) void gemm_3xbf16(
    const float* __restrict__ A1, const int* __restrict__ gidx,
    const float* __restrict__ A2, int K1,
    const float* __restrict__ W, const float* __restrict__ bias,
    const float* __restrict__ res, const int* __restrict__ resIdx,
    const int* __restrict__ dstIdx,
    float* __restrict__ C, int M, int N, int K, int act)
{
    __shared__ uint32_t AsH[2][BM][PA];
    __shared__ uint32_t AsL[2][BM][PA];
    __shared__ uint32_t WsH[2][8][PW];
    __shared__ uint32_t WsL[2][8][PW];

    const int tid  = threadIdx.x;
    const int lane = tid & 31;
    const int wid  = tid >> 5;
    const int row0 = blockIdx.y * BM;
    const int col0 = blockIdx.x * BN;

    // ---- staging mappings ----
    const int aRow = tid >> 1;            // 0..127
    const int aK8  = (tid & 1) * 8;       // 0 or 8 (k offset within tile)
    const int wKr  = (tid >> 5) * 2;      // 0,2,..,14 (k row pair base)
    const int wCol = lane * 4;            // 0..124

    const int K2s = K - K1;               // stride of A2

    const int gRowA = row0 + aRow;
    const bool av = gRowA < M;
    size_t a1off = 0, a2off = 0;
    if (av) {
        int r = gidx ? __ldg(&gidx[gRowA]) : gRowA;
        a1off = (size_t)r * K1;
        a2off = (size_t)gRowA * K2s;
    }
    const int gnW = col0 + wCol;
    const bool wv = gnW < N;              // N%4==0 covers the float4

    // warp tile: 32 (m) x 64 (n); warps 4x2
    const int wm = (wid & 3) * 32;
    const int wn = (wid >> 2) * 64;
    const int grp = lane >> 2;
    const int qid = lane & 3;

    float acc[2][8][4];
    #pragma unroll
    for (int mt = 0; mt < 2; mt++)
        #pragma unroll
        for (int nt = 0; nt < 8; nt++)
            #pragma unroll
            for (int c = 0; c < 4; c++) acc[mt][nt][c] = 0.0f;

    // kg multiple of 4; K%8==0 so a float4 starting below K is fully valid
    auto loadA4 = [&](int kg) -> float4 {
        if (!av || kg >= K) return make_float4(0.f, 0.f, 0.f, 0.f);
        if (kg < K1) return *(const float4*)&A1[a1off + kg];
        return *(const float4*)&A2[a2off + (kg - K1)];
    };
    auto loadW4 = [&](int krow) -> float4 {
        if (!wv || krow >= K) return make_float4(0.f, 0.f, 0.f, 0.f);
        return *(const float4*)&W[(size_t)krow * N + gnW];
    };

    float4 aV0, aV1, wV0, wV1;
    auto prefetch = [&](int k0) {
        aV0 = loadA4(k0 + aK8);
        aV1 = loadA4(k0 + aK8 + 4);
        wV0 = loadW4(k0 + wKr);
        wV1 = loadW4(k0 + wKr + 1);
    };
    auto stage = [&](int buf) {
        // A: pairs along k within one row
        float h0 = bf16_round(aV0.x), h1 = bf16_round(aV0.y),
              h2 = bf16_round(aV0.z), h3 = bf16_round(aV0.w),
              h4 = bf16_round(aV1.x), h5 = bf16_round(aV1.y),
              h6 = bf16_round(aV1.z), h7 = bf16_round(aV1.w);
        uint4 hi = make_uint4(pack_bf16(h0, h1), pack_bf16(h2, h3),
                              pack_bf16(h4, h5), pack_bf16(h6, h7));
        uint4 lo = make_uint4(pack_bf16(aV0.x - h0, aV0.y - h1),
                              pack_bf16(aV0.z - h2, aV0.w - h3),
                              pack_bf16(aV1.x - h4, aV1.y - h5),
                              pack_bf16(aV1.z - h6, aV1.w - h7));
        *(uint4*)&AsH[buf][aRow][aK8 / 2] = hi;
        *(uint4*)&AsL[buf][aRow][aK8 / 2] = lo;
        // W: pairs along k across two k-rows, per column
        float g0 = bf16_round(wV0.x), g1 = bf16_round(wV0.y),
              g2 = bf16_round(wV0.z), g3 = bf16_round(wV0.w),
              g4 = bf16_round(wV1.x), g5 = bf16_round(wV1.y),
              g6 = bf16_round(wV1.z), g7 = bf16_round(wV1.w);
        uint4 whi = make_uint4(pack_bf16(g0, g4), pack_bf16(g1, g5),
                               pack_bf16(g2, g6), pack_bf16(g3, g7));
        uint4 wlo = make_uint4(pack_bf16(wV0.x - g0, wV1.x - g4),
                               pack_bf16(wV0.y - g1, wV1.y - g5),
                               pack_bf16(wV0.z - g2, wV1.z - g6),
                               pack_bf16(wV0.w - g3, wV1.w - g7));
        *(uint4*)&WsH[buf][wKr / 2][wCol] = whi;
        *(uint4*)&WsL[buf][wKr / 2][wCol] = wlo;
    };

    const int nTiles = (K + BK - 1) / BK;

    // prologue: stage tile 0, prefetch tile 1
    prefetch(0);
    stage(0);
    if (nTiles > 1) prefetch(BK);
    __syncthreads();

    for (int t = 0; t < nTiles; t++) {
        const int buf = t & 1;
        if (t + 1 < nTiles) stage(buf ^ 1);
        if (t + 2 < nTiles) prefetch((t + 2) * BK);

        uint32_t ah[2][4], al[2][4];
        #pragma unroll
        for (int mt = 0; mt < 2; mt++) {
            const int ar = wm + 16 * mt + grp;
            ah[mt][0] = AsH[buf][ar    ][qid];
            ah[mt][1] = AsH[buf][ar + 8][qid];
            ah[mt][2] = AsH[buf][ar    ][qid + 4];
            ah[mt][3] = AsH[buf][ar + 8][qid + 4];
            al[mt][0] = AsL[buf][ar    ][qid];
            al[mt][1] = AsL[buf][ar + 8][qid];
            al[mt][2] = AsL[buf][ar    ][qid + 4];
            al[mt][3] = AsL[buf][ar + 8][qid + 4];
        }
        #pragma unroll
        for (int nt = 0; nt < 8; nt++) {
            const int bc = wn + 8 * nt + grp;
            uint32_t bh0 = WsH[buf][qid    ][bc];
            uint32_t bh1 = WsH[buf][qid + 4][bc];
            uint32_t bl0 = WsL[buf][qid    ][bc];
            uint32_t bl1 = WsL[buf][qid + 4][bc];
            #pragma unroll
            for (int mt = 0; mt < 2; mt++) {
                #define MMA_BF16(Afr, B0, B1)                                          \
                    asm volatile(                                                      \
                        "mma.sync.aligned.m16n8k16.row.col.f32.bf16.bf16.f32 "         \
                        "{%0,%1,%2,%3}, {%4,%5,%6,%7}, {%8,%9}, {%0,%1,%2,%3};"        \
                        : "+f"(acc[mt][nt][0]), "+f"(acc[mt][nt][1]),                  \
                          "+f"(acc[mt][nt][2]), "+f"(acc[mt][nt][3])                   \
                        : "r"(Afr[mt][0]), "r"(Afr[mt][1]),                            \
                          "r"(Afr[mt][2]), "r"(Afr[mt][3]),                            \
                          "r"(B0), "r"(B1))
                MMA_BF16(ah, bh0, bh1);   // hi * hi
                MMA_BF16(al, bh0, bh1);   // lo * hi
                MMA_BF16(ah, bl0, bl1);   // hi * lo
                #undef MMA_BF16
            }
        }
        __syncthreads();
    }

    // ---- epilogue: bias (+ gathered residual) -> act -> store/scatter ----
    #pragma unroll
    for (int mt = 0; mt < 2; mt++) {
        #pragma unroll
        for (int rr = 0; rr < 2; rr++) {
            const int gm = row0 + wm + 16 * mt + grp + rr * 8;
            if (gm >= M) continue;
            int drow = 0;
            if (dstIdx) drow = __ldg(&dstIdx[gm]);
            size_t resRow = 0;
            if (res) resRow = (size_t)(resIdx ? __ldg(&resIdx[gm]) : gm) * N;
            #pragma unroll
            for (int nt = 0; nt < 8; nt++) {
                const int gn = col0 + wn + 8 * nt + qid * 2;
                if (gn >= N) continue;   // N even, pair aligned
                float2 bb = __ldg((const float2*)&bias[gn]);
                float v0 = acc[mt][nt][rr * 2 + 0] + bb.x;
                float v1 = acc[mt][nt][rr * 2 + 1] + bb.y;
                if (res) {
                    float2 rv = *(const float2*)&res[resRow + gn];
                    v0 += rv.x; v1 += rv.y;
                }
                if (act) { v0 = silu_f(v0); v1 = silu_f(v1); }
                if (dstIdx) {
                    atomicAdd(&C[(size_t)drow * N + gn],     v0);
                    atomicAdd(&C[(size_t)drow * N + gn + 1], v1);
                } else {
                    *(float2*)&C[(size_t)gm * N + gn] = make_float2(v0, v1);
                }
            }
        }
    }
}

// ---------------- edge gather + Lie bracket -> br (8 edges/block, warp/edge) ----
constexpr int EPB = 8;
__global__ __launch_bounds__(256) void edge_bracket_kernel(
    const float* __restrict__ h, const int* __restrict__ ei,
    const int* __restrict__ sci, const int* __restrict__ scj,
    const int* __restrict__ sck, const float* __restrict__ scc,
    float* __restrict__ br)
{
    __shared__ int   s_i[NNZ_], s_j[NNZ_], s_k[NNZ_];
    __shared__ float s_c[NNZ_];
    __shared__ float hs[EPB][D_], hd[EPB][D_], brs[EPB][D_];

    const int tid = threadIdx.x;
    for (int t = tid; t < NNZ_; t += 256) {
        s_i[t] = __ldg(&sci[t]);
        s_j[t] = __ldg(&scj[t]);
        s_k[t] = __ldg(&sck[t]);
        s_c[t] = __ldg(&scc[t]);
    }
    __syncthreads();

    const int w = tid >> 5, lane = tid & 31;
    const int e = blockIdx.x * EPB + w;
    if (e >= E_) return;
    const int s = __ldg(&ei[e]);
    const int d = __ldg(&ei[E_ + e]);

    const float4* hsrc = (const float4*)(h + (size_t)s * D_);
    const float4* hdst = (const float4*)(h + (size_t)d * D_);
    #pragma unroll
    for (int q = lane; q < D_ / 4; q += 32) {
        ((float4*)hs[w])[q] = hsrc[q];
        ((float4*)hd[w])[q] = hdst[q];
    }
    for (int k = lane; k < D_; k += 32) brs[w][k] = 0.0f;
    __syncwarp();

    #pragma unroll
    for (int t = lane; t < NNZ_; t += 32) {
        float v = s_c[t] * hs[w][s_i[t]] * hd[w][s_j[t]];
        atomicAdd(&brs[w][s_k[t]], v);
    }
    __syncwarp();

    float4* row = (float4*)(br + (size_t)e * D_);
    #pragma unroll
    for (int q = lane; q < D_ / 4; q += 32)
        row[q] = ((const float4*)brs[w])[q];
}

__global__ void zero_kernel(float* __restrict__ p, size_t n) {
    size_t idx = (size_t)blockIdx.x * blockDim.x + threadIdx.x;
    if (idx < n) p[idx] = 0.0f;
}

// ---------------- killing form + pooling (scatter to graphs) ----------------
__global__ __launch_bounds__(128) void killing_pool_kernel(
    const float* __restrict__ h, const int* __restrict__ batch,
    const int* __restrict__ kbr, const int* __restrict__ kbc,
    const float* __restrict__ kbv,
    float* __restrict__ pooled, float* __restrict__ cnt)
{
    const int n = blockIdx.x;
    __shared__ float hrow[D_];
    __shared__ float wsum[4];
    for (int k = threadIdx.x; k < D_; k += 128)
        hrow[k] = h[(size_t)n * D_ + k];
    __syncthreads();

    float s = 0.0f;
    for (int t = threadIdx.x; t < NB_; t += 128)
        s += __ldg(&kbv[t]) * hrow[__ldg(&kbr[t])] * hrow[__ldg(&kbc[t])];
    #pragma unroll
    for (int off = 16; off > 0; off >>= 1)
        s += __shfl_down_sync(0xffffffffu, s, off);
    if ((threadIdx.x & 31) == 0) wsum[threadIdx.x >> 5] = s;
    __syncthreads();

    const int b = __ldg(&batch[n]);
    for (int k = threadIdx.x; k < D_; k += 128)
        atomicAdd(&pooled[b * DP1_ + k], hrow[k]);
    if (threadIdx.x == 0) {
        float ks = wsum[0] + wsum[1] + wsum[2] + wsum[3];
        atomicAdd(&pooled[b * DP1_ + D_], ks);
        atomicAdd(&cnt[b], 1.0f);
    }
}

// ---------------- final MLP per graph ----------------
__global__ __launch_bounds__(256) void final_mlp_kernel(
    const float* __restrict__ pooled, const float* __restrict__ cnt,
    const float* __restrict__ Wo1, const float* __restrict__ bo1,
    const float* __restrict__ Wo2, const float* __restrict__ bo2,
    float* __restrict__ out)
{
    const int g = blockIdx.x;
    __shared__ float p[DP1_];
    __shared__ float hid[HID_];
    const float c = fmaxf(cnt[g], 1.0f);
    for (int k = threadIdx.x; k < DP1_; k += 256)
        p[k] = pooled[g * DP1_ + k] / c;
    __syncthreads();

    const int j = threadIdx.x;
    float s = __ldg(&bo1[j]);
    for (int k = 0; k < DP1_; k++)
        s = fmaf(p[k], __ldg(&Wo1[k * HID_ + j]), s);
    hid[j] = silu_f(s);
    __syncthreads();

    if (j < OUT_) {
        float o = __ldg(&bo2[j]);
        for (int k = 0; k < HID_; k++)
            o = fmaf(hid[k], __ldg(&Wo2[k * OUT_ + j]), o);
        out[g * OUT_ + j] = o;
    }
}

// ---------------- host driver ----------------
static inline dim3 gemm_grid(int M, int N) {
    return dim3((N + BN - 1) / BN, (M + BM - 1) / BM);
}

extern "C" void kernel_launch(void* const* d_in, const int* in_sizes, int n_in,
                              void* d_out, int out_size)
{
    const float* x     = (const float*)d_in[0];
    const int*   ei    = (const int*)  d_in[1];
    const int*   batch = (const int*)  d_in[2];
    const int*   sci   = (const int*)  d_in[3];
    const int*   scj   = (const int*)  d_in[4];
    const int*   sck   = (const int*)  d_in[5];
    const float* scc   = (const float*)d_in[6];
    const int*   kbr   = (const int*)  d_in[7];
    const int*   kbc   = (const int*)  d_in[8];
    const float* kbv   = (const float*)d_in[9];
    const float* Wi1   = (const float*)d_in[10];
    const float* bi1   = (const float*)d_in[11];
    const float* Wi2   = (const float*)d_in[12];
    const float* bi2   = (const float*)d_in[13];
    const float* msgW1 = (const float*)d_in[14];
    const float* msgb1 = (const float*)d_in[15];
    const float* msgW2 = (const float*)d_in[16];
    const float* msgb2 = (const float*)d_in[17];
    const float* updW1 = (const float*)d_in[18];
    const float* updb1 = (const float*)d_in[19];
    const float* updW2 = (const float*)d_in[20];
    const float* updb2 = (const float*)d_in[21];
    const float* Wo1   = (const float*)d_in[22];
    const float* bo1   = (const float*)d_in[23];
    const float* Wo2   = (const float*)d_in[24];
    const float* bo2   = (const float*)d_in[25];

    float *t1, *h, *br, *eH, *agg, *pooled, *cnt, *zbias;
    cudaGetSymbolAddress((void**)&t1,     g_t1);
    cudaGetSymbolAddress((void**)&h,      g_h);
    cudaGetSymbolAddress((void**)&br,     g_br);
    cudaGetSymbolAddress((void**)&eH,     g_eH);
    cudaGetSymbolAddress((void**)&agg,    g_agg);
    cudaGetSymbolAddress((void**)&pooled, g_pooled);
    cudaGetSymbolAddress((void**)&cnt,    g_cnt);
    cudaGetSymbolAddress((void**)&zbias,  g_zbias);

    const int* src = ei;
    const int* dst = ei + E_;

    zero_kernel<<<1, HID_>>>(zbias, HID_);

    // ---- input MLP: h = silu(x@Wi1+b)@Wi2+b ----
    gemm_3xbf16<<<gemm_grid(N_, HID_), 256>>>(
        x,  nullptr, x,  IN_,  Wi1, bi1, nullptr, nullptr, nullptr, t1, N_, HID_, IN_,  1);
    gemm_3xbf16<<<gemm_grid(N_, D_),   256>>>(
        t1, nullptr, t1, HID_, Wi2, bi2, nullptr, nullptr, nullptr, h,  N_, D_,   HID_, 0);

    // ---- message passing layers ----
    for (int l = 0; l < NL_; l++) {
        const float* mW1 = msgW1 + (size_t)l * D2_ * HID_;     // [496][256]
        const float* mb1 = msgb1 + (size_t)l * HID_;
        const float* mW2 = msgW2 + (size_t)l * HID_ * D_;
        const float* mb2 = msgb2 + (size_t)l * D_;
        const float* uW1 = updW1 + (size_t)l * D2_ * HID_;
        const float* ub1 = updb1 + (size_t)l * HID_;
        const float* uW2 = updW2 + (size_t)l * HID_ * D_;
        const float* ub2 = updb2 + (size_t)l * D_;

        edge_bracket_kernel<<<(E_ + EPB - 1) / EPB, 256>>>(h, ei, sci, scj, sck, scc, br);

        // node-level half of message MLP1: hw = h @ mW1[0:D] + mb1   (no act)
        gemm_3xbf16<<<gemm_grid(N_, HID_), 256>>>(
            h, nullptr, h, D_, mW1, mb1, nullptr, nullptr, nullptr, t1, N_, HID_, D_, 0);

        // edge-level half: eH = silu(br @ mW1[D:2D] + hw[src])
        gemm_3xbf16<<<gemm_grid(E_, HID_), 256>>>(
            br, nullptr, br, D_, mW1 + (size_t)D_ * HID_, zbias,
            t1, src, nullptr, eH, E_, HID_, D_, 1);

        // zero agg, then message MLP2 with fused scatter-add into agg
        {
            size_t n = (size_t)N_ * D_;
            zero_kernel<<<(unsigned)((n + 255) / 256), 256>>>(agg, n);
        }
        gemm_3xbf16<<<gemm_grid(E_, D_), 256>>>(
            eH, nullptr, eH, HID_, mW2, mb2, nullptr, nullptr, dst, agg, E_, D_, HID_, 0);

        // update MLP: A = [h | agg]
        gemm_3xbf16<<<gemm_grid(N_, HID_), 256>>>(
            h,  nullptr, agg, D_,  uW1, ub1, nullptr, nullptr, nullptr, t1, N_, HID_, D2_, 1);
        gemm_3xbf16<<<gemm_grid(N_, D_),   256>>>(
            t1, nullptr, t1,  HID_, uW2, ub2, h, nullptr, nullptr, h,  N_, D_,   HID_, 0);
    }

    // ---- killing form + pooling ----
    {
        size_t n = NG_ * DP1_;
        zero_kernel<<<(unsigned)((n + 255) / 256), 256>>>(pooled, n);
        zero_kernel<<<1, NG_>>>(cnt, NG_);
    }
    killing_pool_kernel<<<N_, 128>>>(h, batch, kbr, kbc, kbv, pooled, cnt);

    // ---- final MLP ----
    final_mlp_kernel<<<NG_, 256>>>(pooled, cnt, Wo1, bo1, Wo2, bo2, (float*)d_out);
}